// round 15
// baseline (speedup 1.0000x reference)
#include <cuda_runtime.h>
#include <cuda_fp16.h>
#include <cstdint>

#define BB 4
#define NN 2048
#define CC 1024
#define HH 16
#define DD 64
#define MM (BB*NN)          // 8192

// Scratch (fp16; q,k post-LN; q pre-scaled by 0.125*log2e); [bh][token][d]
__device__ __half g_q[(size_t)MM * CC];
__device__ __half g_k[(size_t)MM * CC];
__device__ __half g_v[(size_t)MM * CC];
// fp16 copies of inputs
__device__ __half g_x1h[(size_t)MM * CC];
__device__ __half g_x2h[(size_t)MM * CC];
__device__ __half g_wqh[(size_t)CC * CC];
__device__ __half g_wkvh[(size_t)CC * 2 * CC];

// ---------------------------------------------------------------------------
// helpers
// ---------------------------------------------------------------------------
__device__ __forceinline__ float ex2(float x) {
    float r;
    asm("ex2.approx.ftz.f32 %0, %1;" : "=f"(r) : "f"(x));
    return r;
}

__device__ __forceinline__ uint32_t packh2(float lo, float hi) {
    __half2 h = __floats2half2_rn(lo, hi);
    return *reinterpret_cast<uint32_t*>(&h);
}

__device__ __forceinline__ uint32_t smem_u32(const void* p) {
    uint32_t a;
    asm("{ .reg .u64 t; cvta.to.shared.u64 t, %1; cvt.u32.u64 %0, t; }" : "=r"(a) : "l"(p));
    return a;
}

__device__ __forceinline__ void cp16(uint32_t dst, const void* src) {
    asm volatile("cp.async.cg.shared.global [%0], [%1], 16;" :: "r"(dst), "l"(src));
}
__device__ __forceinline__ void cp_commit() { asm volatile("cp.async.commit_group;"); }
__device__ __forceinline__ void cp_wait0()  { asm volatile("cp.async.wait_group 0;"); }
__device__ __forceinline__ void cp_wait1()  { asm volatile("cp.async.wait_group 1;"); }

__device__ __forceinline__ void mmah(float c[4], const uint32_t a[4], const uint32_t b[2]) {
    asm volatile(
        "mma.sync.aligned.m16n8k16.row.col.f32.f16.f16.f32 "
        "{%0,%1,%2,%3}, {%4,%5,%6,%7}, {%8,%9}, {%0,%1,%2,%3};\n"
        : "+f"(c[0]), "+f"(c[1]), "+f"(c[2]), "+f"(c[3])
        : "r"(a[0]), "r"(a[1]), "r"(a[2]), "r"(a[3]), "r"(b[0]), "r"(b[1]));
}

__device__ __forceinline__ void ldm2t(uint32_t& r0, uint32_t& r1, uint32_t addr) {
    asm volatile("ldmatrix.sync.aligned.m8n8.x2.trans.shared.b16 {%0,%1}, [%2];"
                 : "=r"(r0), "=r"(r1) : "r"(addr));
}

// ---------------------------------------------------------------------------
// Merged fp32 -> fp16 conversion (x1 | x2 | wq | wkv in one grid)
// ---------------------------------------------------------------------------
__global__ __launch_bounds__(256) void prep_all(
    const float* __restrict__ x1, const float* __restrict__ x2,
    const float* __restrict__ wq, const float* __restrict__ wkv)
{
    int b = blockIdx.x;
    const float* src; __half* dst; int off;
    if (b < 8192)       { src = x1;  dst = g_x1h;  off = b; }
    else if (b < 16384) { src = x2;  dst = g_x2h;  off = b - 8192; }
    else if (b < 17408) { src = wq;  dst = g_wqh;  off = b - 16384; }
    else                { src = wkv; dst = g_wkvh; off = b - 17408; }
    int i = off * 256 + threadIdx.x;
    float4 v = ((const float4*)src)[i];
    uint2 o;
    o.x = packh2(v.x, v.y);
    o.y = packh2(v.z, v.w);
    ((uint2*)dst)[i] = o;
}

// ---------------------------------------------------------------------------
// Projection GEMM (q + kv in one launch), fp16 m16n8k16 MMA, fp32 accum.
// BK=64, 3-stage cp.async pipeline (one barrier + one wait per chunk).
// Block tile 128x128 (2 heads); 4 warps, each 64x64.
// ---------------------------------------------------------------------------
#define PA_ROW 72                       // halves per A row (pad 64->72)
#define PB_ROW 136                      // halves per B row (pad 128->136)
#define ABUF (128*PA_ROW)               // halves
#define BBUF (64*PB_ROW)
#define PROJ_SMEM ((3*ABUF + 3*BBUF) * 2)   // 107520 bytes

__global__ __launch_bounds__(128, 2) void proj_kernel(
    const float* __restrict__ bq, const float* __restrict__ bkv,
    const float* __restrict__ gamq, const float* __restrict__ betq,
    const float* __restrict__ gamk, const float* __restrict__ betk)
{
    extern __shared__ __half smh[];
    __half* Asm = smh;                  // 3 x [128][PA_ROW]
    __half* Bsm = smh + 3 * ABUF;       // 3 x [64][PB_ROW]

    int tid  = threadIdx.x;
    int wid  = tid >> 5, lane = tid & 31;
    int grp  = lane >> 2, l4 = lane & 3;
    int l15  = lane & 15;
    int wm   = wid >> 1, wn = wid & 1;
    int m0   = blockIdx.y << 7;
    int cb   = blockIdx.x;              // 0..23

    const __half *A, *W;
    const float *bias, *gam, *bet;
    __half* Out; int ld, n0, do_ln, is_q;
    if (cb < 8) {
        A = g_x1h; W = g_wqh; bias = bq; ld = CC; n0 = cb << 7;
        Out = g_q; do_ln = 1; is_q = 1; gam = gamq; bet = betq;
    } else {
        int c2 = cb - 8;
        A = g_x2h; W = g_wkvh; bias = bkv; ld = 2 * CC; n0 = c2 << 7; is_q = 0;
        if (c2 < 8) { Out = g_k; do_ln = 1; gam = gamk; bet = betk; }
        else        { Out = g_v; do_ln = 0; gam = gamq; bet = betq; }
    }
    int n0w = n0 + (wn << 6);
    int head = ((cb >= 16) ? (n0w - 1024) : n0w) >> 6;

    float c[4][8][4];
    #pragma unroll
    for (int mf = 0; mf < 4; mf++)
        #pragma unroll
        for (int nf = 0; nf < 8; nf++)
            #pragma unroll
            for (int i = 0; i < 4; i++) c[mf][nf][i] = 0.f;

    uint32_t as_u = smem_u32(Asm), bs_u = smem_u32(Bsm);

    // loader: per buffer-fill, A = 128 rows x 8 chunks, B = 64 rows x 16 chunks
    // pass i (8 passes): A f=i*128+tid -> r=f>>3, q=f&7
    //                    B f=i*128+tid -> r=f>>4, q=f&15
    #define PROJ_LOAD(pb, k0)                                                   \
        {                                                                       \
            uint32_t au = as_u + ((pb) * ABUF) * 2;                             \
            uint32_t bu = bs_u + ((pb) * BBUF) * 2;                             \
            _Pragma("unroll")                                                   \
            for (int i = 0; i < 8; i++) {                                       \
                int f = i * 128 + tid;                                          \
                int ra = f >> 3, qa = f & 7;                                    \
                cp16(au + (ra * PA_ROW + (qa << 3)) * 2,                        \
                     A + (size_t)(m0 + ra) * CC + (k0) + (qa << 3));            \
                int rb = f >> 4, qb = f & 15;                                   \
                if (i < 8) {                                                    \
                    int rbb = rb + ((i >= 4) ? 0 : 0);                          \
                    (void)rbb;                                                  \
                }                                                               \
                cp16(bu + (((f >> 4) & 63) * PB_ROW + (qb << 3)) * 2,           \
                     W + (size_t)((k0) + ((f >> 4) & 63)) * ld + n0 + (qb << 3)); \
            }                                                                   \
            cp_commit();                                                        \
        }
    // Note: A pass covers 8*128/8 = 128 rows (f>>3 in 0..127 over 8 passes);
    //       B pass covers 8*128/16 = 64 rows (f>>4 in 0..63) but 8 passes give
    //       each (row,chunk) exactly once since f spans 0..1023.

    PROJ_LOAD(0, 0)
    PROJ_LOAD(1, 64)

    int buf = 0;
    for (int ch = 0; ch < 16; ch++) {
        if (ch < 15) cp_wait1();
        else         cp_wait0();
        __syncthreads();

        if (ch < 14) {
            int pb = buf + 2; if (pb >= 3) pb -= 3;
            int k0 = (ch + 2) << 6;
            PROJ_LOAD(pb, k0)
        }

        const __half* Ab = Asm + buf * ABUF;
        uint32_t bbu = bs_u + (buf * BBUF) * 2;
        #pragma unroll
        for (int kk = 0; kk < 4; kk++) {
            int kc = (kk << 4) + (l4 << 1);
            uint32_t a[4][4];
            #pragma unroll
            for (int mf = 0; mf < 4; mf++) {
                int r = (wm << 6) + (mf << 4) + grp;
                a[mf][0] = *(const uint32_t*)&Ab[r * PA_ROW + kc];
                a[mf][1] = *(const uint32_t*)&Ab[(r + 8) * PA_ROW + kc];
                a[mf][2] = *(const uint32_t*)&Ab[r * PA_ROW + kc + 8];
                a[mf][3] = *(const uint32_t*)&Ab[(r + 8) * PA_ROW + kc + 8];
            }
            #pragma unroll
            for (int nf = 0; nf < 8; nf++) {
                uint32_t b[2];
                ldm2t(b[0], b[1],
                      bbu + (((kk << 4) + l15) * PB_ROW + (wn << 6) + (nf << 3)) * 2);
                #pragma unroll
                for (int mf = 0; mf < 4; mf++)
                    mmah(c[mf][nf], a[mf], b);
            }
        }
        if (++buf == 3) buf = 0;
    }

    // Epilogue: bias + (optional) LN + (q) log2 scale + fp16 half2 stores
    const float SC = 0.18033688011112042f;   // 0.125 * log2(e)
    #pragma unroll
    for (int mf = 0; mf < 4; mf++) {
        float s0 = 0.f, s1 = 0.f, t0 = 0.f, t1 = 0.f;
        #pragma unroll
        for (int nf = 0; nf < 8; nf++) {
            int col = (nf << 3) + (l4 << 1);
            float b0 = bias[n0w + col], b1 = bias[n0w + col + 1];
            c[mf][nf][0] += b0; c[mf][nf][1] += b1;
            c[mf][nf][2] += b0; c[mf][nf][3] += b1;
            s0 += c[mf][nf][0] + c[mf][nf][1];
            s1 += c[mf][nf][2] + c[mf][nf][3];
            t0 += c[mf][nf][0] * c[mf][nf][0] + c[mf][nf][1] * c[mf][nf][1];
            t1 += c[mf][nf][2] * c[mf][nf][2] + c[mf][nf][3] * c[mf][nf][3];
        }
        #pragma unroll
        for (int off = 1; off <= 2; off <<= 1) {
            s0 += __shfl_xor_sync(0xffffffffu, s0, off);
            s1 += __shfl_xor_sync(0xffffffffu, s1, off);
            t0 += __shfl_xor_sync(0xffffffffu, t0, off);
            t1 += __shfl_xor_sync(0xffffffffu, t1, off);
        }
        float mean0 = 0.f, mean1 = 0.f, inv0 = 1.f, inv1 = 1.f;
        if (do_ln) {
            mean0 = s0 * 0.015625f;
            mean1 = s1 * 0.015625f;
            inv0 = rsqrtf(t0 * 0.015625f - mean0 * mean0 + 1e-5f);
            inv1 = rsqrtf(t1 * 0.015625f - mean1 * mean1 + 1e-5f);
        }

        int r0 = (wm << 6) + (mf << 4) + grp;
        int m = m0 + r0;
        int b = m >> 11, nseq = m & 2047;
        size_t base0 = (((size_t)(b * HH + head)) * NN + nseq) * DD;
        size_t base1 = base0 + (size_t)8 * DD;
        #pragma unroll
        for (int nf = 0; nf < 8; nf++) {
            int col = (nf << 3) + (l4 << 1);
            float y0 = c[mf][nf][0], y1 = c[mf][nf][1];
            float y2 = c[mf][nf][2], y3 = c[mf][nf][3];
            if (do_ln) {
                float g0 = gam[col], g1 = gam[col + 1];
                float e0 = bet[col], e1 = bet[col + 1];
                y0 = (y0 - mean0) * inv0 * g0 + e0;
                y1 = (y1 - mean0) * inv0 * g1 + e1;
                y2 = (y2 - mean1) * inv1 * g0 + e0;
                y3 = (y3 - mean1) * inv1 * g1 + e1;
            }
            if (is_q) { y0 *= SC; y1 *= SC; y2 *= SC; y3 *= SC; }
            *(uint32_t*)&Out[base0 + col] = packh2(y0, y1);
            *(uint32_t*)&Out[base1 + col] = packh2(y2, y3);
        }
    }
}

// ---------------------------------------------------------------------------
// Flash attention (fp16 m16n8k16 MMA, fp32 accum), unnormalized exp2.
// 3-stage K/V pipeline: ONE barrier + one wait per 64-key tile.
// Q/K fragments via packed LDS.32; V via ldmatrix.trans; P packed from S regs.
// 72 KB smem -> 2 CTAs/SM.
// ---------------------------------------------------------------------------
#define AROW 72                         // halves per smem row (pad 64->72)
#define QS_H (128*AROW)
#define KS_H (64*AROW)
#define VS_H (64*AROW)
#define ATTN_SMEM ((QS_H + 3*KS_H + 3*VS_H) * 2)   // 73728 bytes

__global__ __launch_bounds__(128, 2) void attn_kernel(float* __restrict__ out)
{
    extern __shared__ __half smh[];
    __half* Qs  = smh;                  // [128][AROW]
    __half* Ksb = smh + QS_H;           // 3 x [64][AROW]
    __half* Vsb = smh + QS_H + 3 * KS_H;

    int tid = threadIdx.x;
    int wid = tid >> 5, lane = tid & 31;
    int grp = lane >> 2, l4 = lane & 3;
    int l15 = lane & 15;
    int bh = blockIdx.y, qt = blockIdx.x;
    int mb = wid << 5;

    const __half* qb = g_q + (size_t)bh * (NN * 64) + (size_t)qt * (128 * 64);
    const __half* kb = g_k + (size_t)bh * (NN * 64);
    const __half* vb = g_v + (size_t)bh * (NN * 64);

    uint32_t qs_u = smem_u32(Qs), ks_u = smem_u32(Ksb), vs_u = smem_u32(Vsb);

    // prologue: group 0 (Q + K0/V0) -> buf0, group 1 (K1/V1) -> buf1
    #pragma unroll
    for (int i = 0; i < 8; i++) {
        int f = i * 128 + tid;
        int r = f >> 3, q = f & 7;
        cp16(qs_u + (r * AROW + (q << 3)) * 2, qb + r * 64 + (q << 3));
    }
    #pragma unroll
    for (int i = 0; i < 4; i++) {
        int f = i * 128 + tid;
        int r = f >> 3, q = f & 7;
        cp16(ks_u + (r * AROW + (q << 3)) * 2, kb + r * 64 + (q << 3));
        cp16(vs_u + (r * AROW + (q << 3)) * 2, vb + r * 64 + (q << 3));
    }
    cp_commit();
    #pragma unroll
    for (int i = 0; i < 4; i++) {
        int f = i * 128 + tid;
        int r = f >> 3, q = f & 7;
        cp16(ks_u + (KS_H + r * AROW + (q << 3)) * 2, kb + 4096 + r * 64 + (q << 3));
        cp16(vs_u + (VS_H + r * AROW + (q << 3)) * 2, vb + 4096 + r * 64 + (q << 3));
    }
    cp_commit();

    float o[2][8][4];
    #pragma unroll
    for (int mf = 0; mf < 2; mf++)
        #pragma unroll
        for (int df = 0; df < 8; df++)
            #pragma unroll
            for (int i = 0; i < 4; i++) o[mf][df][i] = 0.f;
    float l_i[4] = {0.f, 0.f, 0.f, 0.f};

    int buf = 0;
    for (int kt = 0; kt < 32; kt++) {
        if (kt < 31) cp_wait1();       // drain tile kt; kt+1 stays in flight
        else         cp_wait0();
        __syncthreads();               // tile kt visible; all warps finished kt-1

        // issue tile kt+2 into buffer (kt+2)%3 == (kt-1)%3 (readers done)
        if (kt < 30) {
            int pb = buf + 2; if (pb >= 3) pb -= 3;
            const __half* kn = kb + (kt + 2) * 4096;
            const __half* vn = vb + (kt + 2) * 4096;
            uint32_t kdst = ks_u + (pb * KS_H) * 2;
            uint32_t vdst = vs_u + (pb * VS_H) * 2;
            #pragma unroll
            for (int i = 0; i < 4; i++) {
                int f = i * 128 + tid;
                int r = f >> 3, q = f & 7;
                cp16(kdst + (r * AROW + (q << 3)) * 2, kn + r * 64 + (q << 3));
                cp16(vdst + (r * AROW + (q << 3)) * 2, vn + r * 64 + (q << 3));
            }
            cp_commit();
        }

        const __half* Ks = Ksb + buf * KS_H;
        uint32_t vbu = vs_u + (buf * VS_H) * 2;

        // S = Q @ K^T (log2 domain)
        float s[2][8][4];
        #pragma unroll
        for (int mf = 0; mf < 2; mf++)
            #pragma unroll
            for (int nf = 0; nf < 8; nf++)
                #pragma unroll
                for (int i = 0; i < 4; i++) s[mf][nf][i] = 0.f;

        #pragma unroll
        for (int kk = 0; kk < 4; kk++) {
            int kc = (kk << 4) + (l4 << 1);
            uint32_t a[2][4], b[8][2];
            #pragma unroll
            for (int mf = 0; mf < 2; mf++) {
                int r = mb + (mf << 4) + grp;
                a[mf][0] = *(const uint32_t*)&Qs[r * AROW + kc];
                a[mf][1] = *(const uint32_t*)&Qs[(r + 8) * AROW + kc];
                a[mf][2] = *(const uint32_t*)&Qs[r * AROW + kc + 8];
                a[mf][3] = *(const uint32_t*)&Qs[(r + 8) * AROW + kc + 8];
            }
            #pragma unroll
            for (int nf = 0; nf < 8; nf++) {
                int n = (nf << 3) + grp;
                b[nf][0] = *(const uint32_t*)&Ks[n * AROW + kc];
                b[nf][1] = *(const uint32_t*)&Ks[n * AROW + kc + 8];
            }
            #pragma unroll
            for (int mf = 0; mf < 2; mf++)
                #pragma unroll
                for (int nf = 0; nf < 8; nf++)
                    mmah(s[mf][nf], a[mf], b[nf]);
        }

        // p = exp2(s); per-thread row sums
        #pragma unroll
        for (int mf = 0; mf < 2; mf++)
            #pragma unroll
            for (int nf = 0; nf < 8; nf++) {
                float p0 = ex2(s[mf][nf][0]);
                float p1 = ex2(s[mf][nf][1]);
                float p2 = ex2(s[mf][nf][2]);
                float p3 = ex2(s[mf][nf][3]);
                s[mf][nf][0] = p0; s[mf][nf][1] = p1;
                s[mf][nf][2] = p2; s[mf][nf][3] = p3;
                l_i[mf << 1]       += p0 + p1;
                l_i[(mf << 1) + 1] += p2 + p3;
            }

        // O += P @ V : P packed from S regs; V b-frags via ldmatrix.trans
        #pragma unroll
        for (int kk = 0; kk < 4; kk++) {
            uint32_t b[8][2];
            #pragma unroll
            for (int df = 0; df < 8; df++)
                ldm2t(b[df][0], b[df][1],
                      vbu + (((kk << 4) + l15) * AROW + (df << 3)) * 2);
            #pragma unroll
            for (int mf = 0; mf < 2; mf++) {
                uint32_t a[4];
                a[0] = packh2(s[mf][kk << 1][0],        s[mf][kk << 1][1]);
                a[1] = packh2(s[mf][kk << 1][2],        s[mf][kk << 1][3]);
                a[2] = packh2(s[mf][(kk << 1) + 1][0],  s[mf][(kk << 1) + 1][1]);
                a[3] = packh2(s[mf][(kk << 1) + 1][2],  s[mf][(kk << 1) + 1][3]);
                #pragma unroll
                for (int df = 0; df < 8; df++)
                    mmah(o[mf][df], a, b[df]);
            }
        }

        if (++buf == 3) buf = 0;
    }

    // epilogue: reduce row sums across quad, normalize, write out[b][n][h*64+d]
    #pragma unroll
    for (int si = 0; si < 4; si++) {
        l_i[si] += __shfl_xor_sync(0xffffffffu, l_i[si], 1);
        l_i[si] += __shfl_xor_sync(0xffffffffu, l_i[si], 2);
    }
    int b = bh >> 4, h = bh & 15;
    #pragma unroll
    for (int mf = 0; mf < 2; mf++) {
        #pragma unroll
        for (int rr = 0; rr < 2; rr++) {
            int si = (mf << 1) + rr;
            float inv = 1.f / l_i[si];
            int n = (qt << 7) + mb + (mf << 4) + grp + (rr << 3);
            size_t base = ((size_t)(b * NN + n)) * CC + (h << 6);
            #pragma unroll
            for (int df = 0; df < 8; df++) {
                int col = (df << 3) + (l4 << 1);
                float2 vo = make_float2(o[mf][df][rr * 2] * inv,
                                        o[mf][df][rr * 2 + 1] * inv);
                *(float2*)&out[base + col] = vo;
            }
        }
    }
}

// ---------------------------------------------------------------------------
extern "C" void kernel_launch(void* const* d_in, const int* in_sizes, int n_in,
                              void* d_out, int out_size)
{
    const float* x1   = (const float*)d_in[0];
    const float* x2   = (const float*)d_in[1];
    const float* wq   = (const float*)d_in[2];
    const float* bq   = (const float*)d_in[3];
    const float* wkv  = (const float*)d_in[4];
    const float* bkv  = (const float*)d_in[5];
    const float* gmq  = (const float*)d_in[6];
    const float* btq  = (const float*)d_in[7];
    const float* gmk  = (const float*)d_in[8];
    const float* btk  = (const float*)d_in[9];
    float* out = (float*)d_out;

    cudaFuncSetAttribute(attn_kernel, cudaFuncAttributeMaxDynamicSharedMemorySize, ATTN_SMEM);
    cudaFuncSetAttribute(proj_kernel, cudaFuncAttributeMaxDynamicSharedMemorySize, PROJ_SMEM);

    prep_all<<<19456, 256>>>(x1, x2, wq, wkv);

    proj_kernel<<<dim3(24, MM / 128), 128, PROJ_SMEM>>>(bq, bkv, gmq, btq, gmk, btk);

    attn_kernel<<<dim3(NN / 128, BB * HH), 128, ATTN_SMEM>>>(out);
}

// round 16
// speedup vs baseline: 1.0486x; 1.0486x over previous
#include <cuda_runtime.h>
#include <cuda_fp16.h>
#include <cstdint>

#define BB 4
#define NN 2048
#define CC 1024
#define HH 16
#define DD 64
#define MM (BB*NN)          // 8192

// Scratch (fp16; q,k post-LN; q pre-scaled by 0.125*log2e); [bh][token][d]
__device__ __half g_q[(size_t)MM * CC];
__device__ __half g_k[(size_t)MM * CC];
__device__ __half g_v[(size_t)MM * CC];
// fp16 copies of inputs
__device__ __half g_x1h[(size_t)MM * CC];
__device__ __half g_x2h[(size_t)MM * CC];
__device__ __half g_wqh[(size_t)CC * CC];
__device__ __half g_wkvh[(size_t)CC * 2 * CC];

// ---------------------------------------------------------------------------
// helpers
// ---------------------------------------------------------------------------
__device__ __forceinline__ float ex2(float x) {
    float r;
    asm("ex2.approx.ftz.f32 %0, %1;" : "=f"(r) : "f"(x));
    return r;
}

__device__ __forceinline__ uint32_t packh2(float lo, float hi) {
    __half2 h = __floats2half2_rn(lo, hi);
    return *reinterpret_cast<uint32_t*>(&h);
}

__device__ __forceinline__ uint32_t smem_u32(const void* p) {
    uint32_t a;
    asm("{ .reg .u64 t; cvta.to.shared.u64 t, %1; cvt.u32.u64 %0, t; }" : "=r"(a) : "l"(p));
    return a;
}

__device__ __forceinline__ void cp16(uint32_t dst, const void* src) {
    asm volatile("cp.async.cg.shared.global [%0], [%1], 16;" :: "r"(dst), "l"(src));
}
__device__ __forceinline__ void cp_commit() { asm volatile("cp.async.commit_group;"); }
__device__ __forceinline__ void cp_wait0()  { asm volatile("cp.async.wait_group 0;"); }
__device__ __forceinline__ void cp_wait1()  { asm volatile("cp.async.wait_group 1;"); }

__device__ __forceinline__ void mmah(float c[4], const uint32_t a[4], const uint32_t b[2]) {
    asm volatile(
        "mma.sync.aligned.m16n8k16.row.col.f32.f16.f16.f32 "
        "{%0,%1,%2,%3}, {%4,%5,%6,%7}, {%8,%9}, {%0,%1,%2,%3};\n"
        : "+f"(c[0]), "+f"(c[1]), "+f"(c[2]), "+f"(c[3])
        : "r"(a[0]), "r"(a[1]), "r"(a[2]), "r"(a[3]), "r"(b[0]), "r"(b[1]));
}

__device__ __forceinline__ void ldm2t(uint32_t& r0, uint32_t& r1, uint32_t addr) {
    asm volatile("ldmatrix.sync.aligned.m8n8.x2.trans.shared.b16 {%0,%1}, [%2];"
                 : "=r"(r0), "=r"(r1) : "r"(addr));
}

// ---------------------------------------------------------------------------
// Merged fp32 -> fp16 conversion (x1 | x2 | wq | wkv in one grid)
// block counts (float4 granularity / 256 threads): 8192 | 8192 | 1024 | 2048
// ---------------------------------------------------------------------------
__global__ __launch_bounds__(256) void prep_all(
    const float* __restrict__ x1, const float* __restrict__ x2,
    const float* __restrict__ wq, const float* __restrict__ wkv)
{
    int b = blockIdx.x;
    const float* src; __half* dst; int off;
    if (b < 8192)       { src = x1;  dst = g_x1h;  off = b; }
    else if (b < 16384) { src = x2;  dst = g_x2h;  off = b - 8192; }
    else if (b < 17408) { src = wq;  dst = g_wqh;  off = b - 16384; }
    else                { src = wkv; dst = g_wkvh; off = b - 17408; }
    int i = off * 256 + threadIdx.x;
    float4 v = ((const float4*)src)[i];
    uint2 o;
    o.x = packh2(v.x, v.y);
    o.y = packh2(v.z, v.w);
    ((uint2*)dst)[i] = o;
}

// ---------------------------------------------------------------------------
// Projection GEMM (q + kv in one launch), fp16 m16n8k16 MMA, fp32 accum.
// BK=32, 3-stage cp.async pipeline (one barrier + one wait per chunk).
// Block tile 128x128 (2 heads); 4 warps, each 64x64.
// A (x rows) via packed LDS.32; B (W [k][n]) via ldmatrix.x2.trans.
// Epilogue: bias + per-head LN (q,k), q log2-scale, fp16 half2 stores.
// ---------------------------------------------------------------------------
#define PA_ROW 40                       // halves per A row (pad 32->40)
#define PB_ROW 136                      // halves per B row (pad 128->136)
#define ABUF (128*PA_ROW)               // halves
#define BBUF (32*PB_ROW)
#define PROJ_SMEM ((3*ABUF + 3*BBUF) * 2)   // 56832 bytes

__global__ __launch_bounds__(128, 2) void proj_kernel(
    const float* __restrict__ bq, const float* __restrict__ bkv,
    const float* __restrict__ gamq, const float* __restrict__ betq,
    const float* __restrict__ gamk, const float* __restrict__ betk)
{
    extern __shared__ __half smh[];
    __half* Asm = smh;                  // 3 x [128][PA_ROW]
    __half* Bsm = smh + 3 * ABUF;       // 3 x [32][PB_ROW]

    int tid  = threadIdx.x;
    int wid  = tid >> 5, lane = tid & 31;
    int grp  = lane >> 2, l4 = lane & 3;
    int l15  = lane & 15;
    int wm   = wid >> 1, wn = wid & 1;
    int m0   = blockIdx.y << 7;
    int cb   = blockIdx.x;              // 0..23

    const __half *A, *W;
    const float *bias, *gam, *bet;
    __half* Out; int ld, n0, do_ln, is_q;
    if (cb < 8) {
        A = g_x1h; W = g_wqh; bias = bq; ld = CC; n0 = cb << 7;
        Out = g_q; do_ln = 1; is_q = 1; gam = gamq; bet = betq;
    } else {
        int c2 = cb - 8;
        A = g_x2h; W = g_wkvh; bias = bkv; ld = 2 * CC; n0 = c2 << 7; is_q = 0;
        if (c2 < 8) { Out = g_k; do_ln = 1; gam = gamk; bet = betk; }
        else        { Out = g_v; do_ln = 0; gam = gamq; bet = betq; }
    }
    int n0w = n0 + (wn << 6);
    int head = ((cb >= 16) ? (n0w - 1024) : n0w) >> 6;

    float c[4][8][4];
    #pragma unroll
    for (int mf = 0; mf < 4; mf++)
        #pragma unroll
        for (int nf = 0; nf < 8; nf++)
            #pragma unroll
            for (int i = 0; i < 4; i++) c[mf][nf][i] = 0.f;

    uint32_t as_u = smem_u32(Asm), bs_u = smem_u32(Bsm);

    // loaders: A 128 rows x 4 chunks(16B); B 32 rows x 16 chunks
    int aR = tid >> 2, aQ = tid & 3;         // + i*32 rows per pass (4 passes)
    int bR = tid >> 4, bQ = tid & 15;        // + i*8 rows per pass (4 passes)

    // prologue: chunk 0 -> buf0, chunk 1 -> buf1
    #pragma unroll
    for (int i = 0; i < 4; i++) {
        int r = aR + (i << 5);
        cp16(as_u + (r * PA_ROW + (aQ << 3)) * 2, A + (size_t)(m0 + r) * CC + (aQ << 3));
        int rb = bR + (i << 3);
        cp16(bs_u + (rb * PB_ROW + (bQ << 3)) * 2, W + (size_t)rb * ld + n0 + (bQ << 3));
    }
    cp_commit();
    #pragma unroll
    for (int i = 0; i < 4; i++) {
        int r = aR + (i << 5);
        cp16(as_u + (ABUF + r * PA_ROW + (aQ << 3)) * 2,
             A + (size_t)(m0 + r) * CC + 32 + (aQ << 3));
        int rb = bR + (i << 3);
        cp16(bs_u + (BBUF + rb * PB_ROW + (bQ << 3)) * 2,
             W + (size_t)(32 + rb) * ld + n0 + (bQ << 3));
    }
    cp_commit();

    int buf = 0;
    for (int ch = 0; ch < 32; ch++) {
        if (ch < 31) cp_wait1();
        else         cp_wait0();
        __syncthreads();

        if (ch < 30) {
            int pb = buf + 2; if (pb >= 3) pb -= 3;
            int k0 = (ch + 2) << 5;
            #pragma unroll
            for (int i = 0; i < 4; i++) {
                int r = aR + (i << 5);
                cp16(as_u + (pb * ABUF + r * PA_ROW + (aQ << 3)) * 2,
                     A + (size_t)(m0 + r) * CC + k0 + (aQ << 3));
                int rb = bR + (i << 3);
                cp16(bs_u + (pb * BBUF + rb * PB_ROW + (bQ << 3)) * 2,
                     W + (size_t)(k0 + rb) * ld + n0 + (bQ << 3));
            }
            cp_commit();
        }

        const __half* Ab = Asm + buf * ABUF;
        uint32_t bbu = bs_u + (buf * BBUF) * 2;
        #pragma unroll
        for (int kk = 0; kk < 2; kk++) {
            int kc = (kk << 4) + (l4 << 1);
            uint32_t a[4][4];
            #pragma unroll
            for (int mf = 0; mf < 4; mf++) {
                int r = (wm << 6) + (mf << 4) + grp;
                a[mf][0] = *(const uint32_t*)&Ab[r * PA_ROW + kc];
                a[mf][1] = *(const uint32_t*)&Ab[(r + 8) * PA_ROW + kc];
                a[mf][2] = *(const uint32_t*)&Ab[r * PA_ROW + kc + 8];
                a[mf][3] = *(const uint32_t*)&Ab[(r + 8) * PA_ROW + kc + 8];
            }
            #pragma unroll
            for (int nf = 0; nf < 8; nf++) {
                uint32_t b[2];
                ldm2t(b[0], b[1],
                      bbu + (((kk << 4) + l15) * PB_ROW + (wn << 6) + (nf << 3)) * 2);
                #pragma unroll
                for (int mf = 0; mf < 4; mf++)
                    mmah(c[mf][nf], a[mf], b);
            }
        }
        if (++buf == 3) buf = 0;
    }

    // Epilogue: bias + (optional) LN + (q) log2 scale + fp16 half2 stores
    const float SC = 0.18033688011112042f;   // 0.125 * log2(e)
    #pragma unroll
    for (int mf = 0; mf < 4; mf++) {
        float s0 = 0.f, s1 = 0.f, t0 = 0.f, t1 = 0.f;
        #pragma unroll
        for (int nf = 0; nf < 8; nf++) {
            int col = (nf << 3) + (l4 << 1);
            float b0 = bias[n0w + col], b1 = bias[n0w + col + 1];
            c[mf][nf][0] += b0; c[mf][nf][1] += b1;
            c[mf][nf][2] += b0; c[mf][nf][3] += b1;
            s0 += c[mf][nf][0] + c[mf][nf][1];
            s1 += c[mf][nf][2] + c[mf][nf][3];
            t0 += c[mf][nf][0] * c[mf][nf][0] + c[mf][nf][1] * c[mf][nf][1];
            t1 += c[mf][nf][2] * c[mf][nf][2] + c[mf][nf][3] * c[mf][nf][3];
        }
        #pragma unroll
        for (int off = 1; off <= 2; off <<= 1) {
            s0 += __shfl_xor_sync(0xffffffffu, s0, off);
            s1 += __shfl_xor_sync(0xffffffffu, s1, off);
            t0 += __shfl_xor_sync(0xffffffffu, t0, off);
            t1 += __shfl_xor_sync(0xffffffffu, t1, off);
        }
        float mean0 = 0.f, mean1 = 0.f, inv0 = 1.f, inv1 = 1.f;
        if (do_ln) {
            mean0 = s0 * 0.015625f;
            mean1 = s1 * 0.015625f;
            inv0 = rsqrtf(t0 * 0.015625f - mean0 * mean0 + 1e-5f);
            inv1 = rsqrtf(t1 * 0.015625f - mean1 * mean1 + 1e-5f);
        }

        int r0 = (wm << 6) + (mf << 4) + grp;
        int m = m0 + r0;
        int b = m >> 11, nseq = m & 2047;
        size_t base0 = (((size_t)(b * HH + head)) * NN + nseq) * DD;
        size_t base1 = base0 + (size_t)8 * DD;
        #pragma unroll
        for (int nf = 0; nf < 8; nf++) {
            int col = (nf << 3) + (l4 << 1);
            float y0 = c[mf][nf][0], y1 = c[mf][nf][1];
            float y2 = c[mf][nf][2], y3 = c[mf][nf][3];
            if (do_ln) {
                float g0 = gam[col], g1 = gam[col + 1];
                float e0 = bet[col], e1 = bet[col + 1];
                y0 = (y0 - mean0) * inv0 * g0 + e0;
                y1 = (y1 - mean0) * inv0 * g1 + e1;
                y2 = (y2 - mean1) * inv1 * g0 + e0;
                y3 = (y3 - mean1) * inv1 * g1 + e1;
            }
            if (is_q) { y0 *= SC; y1 *= SC; y2 *= SC; y3 *= SC; }
            *(uint32_t*)&Out[base0 + col] = packh2(y0, y1);
            *(uint32_t*)&Out[base1 + col] = packh2(y2, y3);
        }
    }
}

// ---------------------------------------------------------------------------
// Flash attention (fp16 m16n8k16 MMA, fp32 accum), unnormalized exp2.
// Q/K fragments via packed LDS.32 (natural [token][d]); V via ldmatrix.trans.
// S-accumulator packs directly into the PV A-fragment (adjacent pairs).
// exp2 interleaved into the PV MMA stream. K/V double-buffered. 54 KB smem.
// ---------------------------------------------------------------------------
#define AROW 72                         // halves per smem row (pad 64->72)
#define QS_H (128*AROW)
#define KS_H (64*AROW)
#define VS_H (64*AROW)
#define ATTN_SMEM ((QS_H + 2*KS_H + 2*VS_H) * 2)   // 55296 bytes

__global__ __launch_bounds__(128, 2) void attn_kernel(float* __restrict__ out)
{
    extern __shared__ __half smh[];
    __half* Qs  = smh;                  // [128][AROW]
    __half* Ksb = smh + QS_H;           // 2 x [64][AROW]
    __half* Vsb = smh + QS_H + 2 * KS_H;

    int tid = threadIdx.x;
    int wid = tid >> 5, lane = tid & 31;
    int grp = lane >> 2, l4 = lane & 3;
    int l15 = lane & 15;
    int bh = blockIdx.y, qt = blockIdx.x;
    int mb = wid << 5;

    const __half* qb = g_q + (size_t)bh * (NN * 64) + (size_t)qt * (128 * 64);
    const __half* kb = g_k + (size_t)bh * (NN * 64);
    const __half* vb = g_v + (size_t)bh * (NN * 64);

    uint32_t qs_u = smem_u32(Qs), ks_u = smem_u32(Ksb), vs_u = smem_u32(Vsb);

    // prologue: Q + K0/V0 (group A), then K1/V1 (group B)
    #pragma unroll
    for (int i = 0; i < 8; i++) {
        int f = i * 128 + tid;
        int r = f >> 3, q = f & 7;
        cp16(qs_u + (r * AROW + (q << 3)) * 2, qb + r * 64 + (q << 3));
    }
    #pragma unroll
    for (int i = 0; i < 4; i++) {
        int f = i * 128 + tid;
        int r = f >> 3, q = f & 7;
        cp16(ks_u + (r * AROW + (q << 3)) * 2, kb + r * 64 + (q << 3));
        cp16(vs_u + (r * AROW + (q << 3)) * 2, vb + r * 64 + (q << 3));
    }
    cp_commit();
    #pragma unroll
    for (int i = 0; i < 4; i++) {
        int f = i * 128 + tid;
        int r = f >> 3, q = f & 7;
        cp16(ks_u + (KS_H + r * AROW + (q << 3)) * 2, kb + 4096 + r * 64 + (q << 3));
        cp16(vs_u + (VS_H + r * AROW + (q << 3)) * 2, vb + 4096 + r * 64 + (q << 3));
    }
    cp_commit();
    cp_wait1();        // group A complete
    __syncthreads();

    float o[2][8][4];
    #pragma unroll
    for (int mf = 0; mf < 2; mf++)
        #pragma unroll
        for (int df = 0; df < 8; df++)
            #pragma unroll
            for (int i = 0; i < 4; i++) o[mf][df][i] = 0.f;
    float l_i[4] = {0.f, 0.f, 0.f, 0.f};

    for (int kt = 0; kt < 32; kt++) {
        int buf = kt & 1;
        const __half* Ks = Ksb + buf * KS_H;
        uint32_t vbu = vs_u + (buf * VS_H) * 2;

        // S = Q @ K^T (log2 domain)
        float s[2][8][4];
        #pragma unroll
        for (int mf = 0; mf < 2; mf++)
            #pragma unroll
            for (int nf = 0; nf < 8; nf++)
                #pragma unroll
                for (int i = 0; i < 4; i++) s[mf][nf][i] = 0.f;

        #pragma unroll
        for (int kk = 0; kk < 4; kk++) {
            int kc = (kk << 4) + (l4 << 1);
            uint32_t a[2][4], b[8][2];
            #pragma unroll
            for (int mf = 0; mf < 2; mf++) {
                int r = mb + (mf << 4) + grp;
                a[mf][0] = *(const uint32_t*)&Qs[r * AROW + kc];
                a[mf][1] = *(const uint32_t*)&Qs[(r + 8) * AROW + kc];
                a[mf][2] = *(const uint32_t*)&Qs[r * AROW + kc + 8];
                a[mf][3] = *(const uint32_t*)&Qs[(r + 8) * AROW + kc + 8];
            }
            #pragma unroll
            for (int nf = 0; nf < 8; nf++) {
                int n = (nf << 3) + grp;
                b[nf][0] = *(const uint32_t*)&Ks[n * AROW + kc];
                b[nf][1] = *(const uint32_t*)&Ks[n * AROW + kc + 8];
            }
            #pragma unroll
            for (int mf = 0; mf < 2; mf++)
                #pragma unroll
                for (int nf = 0; nf < 8; nf++)
                    mmah(s[mf][nf], a[mf], b[nf]);
        }

        // exp2 of score-groups 0,1 (feeds PV kk=0)
        #pragma unroll
        for (int nf = 0; nf < 2; nf++)
            #pragma unroll
            for (int mf = 0; mf < 2; mf++) {
                float p0 = ex2(s[mf][nf][0]);
                float p1 = ex2(s[mf][nf][1]);
                float p2 = ex2(s[mf][nf][2]);
                float p3 = ex2(s[mf][nf][3]);
                s[mf][nf][0] = p0; s[mf][nf][1] = p1;
                s[mf][nf][2] = p2; s[mf][nf][3] = p3;
                l_i[mf << 1]       += p0 + p1;
                l_i[(mf << 1) + 1] += p2 + p3;
            }

        // O += P @ V, exp2 of groups 2k+2,2k+3 interleaved with PV step kk
        #pragma unroll
        for (int kk = 0; kk < 4; kk++) {
            // exp2 for the NEXT PV step (groups 2kk+2, 2kk+3)
            if (kk < 3) {
                #pragma unroll
                for (int j = 0; j < 2; j++) {
                    int nf = (kk << 1) + 2 + j;
                    #pragma unroll
                    for (int mf = 0; mf < 2; mf++) {
                        float p0 = ex2(s[mf][nf][0]);
                        float p1 = ex2(s[mf][nf][1]);
                        float p2 = ex2(s[mf][nf][2]);
                        float p3 = ex2(s[mf][nf][3]);
                        s[mf][nf][0] = p0; s[mf][nf][1] = p1;
                        s[mf][nf][2] = p2; s[mf][nf][3] = p3;
                        l_i[mf << 1]       += p0 + p1;
                        l_i[(mf << 1) + 1] += p2 + p3;
                    }
                }
            }
            uint32_t b[8][2];
            #pragma unroll
            for (int df = 0; df < 8; df++)
                ldm2t(b[df][0], b[df][1],
                      vbu + (((kk << 4) + l15) * AROW + (df << 3)) * 2);
            #pragma unroll
            for (int mf = 0; mf < 2; mf++) {
                uint32_t a[4];
                a[0] = packh2(s[mf][kk << 1][0],        s[mf][kk << 1][1]);
                a[1] = packh2(s[mf][kk << 1][2],        s[mf][kk << 1][3]);
                a[2] = packh2(s[mf][(kk << 1) + 1][0],  s[mf][(kk << 1) + 1][1]);
                a[3] = packh2(s[mf][(kk << 1) + 1][2],  s[mf][(kk << 1) + 1][3]);
                #pragma unroll
                for (int df = 0; df < 8; df++)
                    mmah(o[mf][df], a, b[df]);
            }
        }

        if (kt < 31) {
            __syncthreads();       // all warps done with buf
            if (kt < 30) {
                const __half* kn = kb + (kt + 2) * 4096;
                const __half* vn = vb + (kt + 2) * 4096;
                uint32_t kdst = ks_u + (buf * KS_H) * 2;
                uint32_t vdst = vs_u + (buf * VS_H) * 2;
                #pragma unroll
                for (int i = 0; i < 4; i++) {
                    int f = i * 128 + tid;
                    int r = f >> 3, q = f & 7;
                    cp16(kdst + (r * AROW + (q << 3)) * 2, kn + r * 64 + (q << 3));
                    cp16(vdst + (r * AROW + (q << 3)) * 2, vn + r * 64 + (q << 3));
                }
                cp_commit();
                cp_wait1();        // group kt+1 complete
            } else {
                cp_wait0();
            }
            __syncthreads();       // next buffer visible
        }
    }

    // epilogue: reduce row sums across quad, normalize, write out[b][n][h*64+d]
    #pragma unroll
    for (int si = 0; si < 4; si++) {
        l_i[si] += __shfl_xor_sync(0xffffffffu, l_i[si], 1);
        l_i[si] += __shfl_xor_sync(0xffffffffu, l_i[si], 2);
    }
    int b = bh >> 4, h = bh & 15;
    #pragma unroll
    for (int mf = 0; mf < 2; mf++) {
        #pragma unroll
        for (int rr = 0; rr < 2; rr++) {
            int si = (mf << 1) + rr;
            float inv = 1.f / l_i[si];
            int n = (qt << 7) + mb + (mf << 4) + grp + (rr << 3);
            size_t base = ((size_t)(b * NN + n)) * CC + (h << 6);
            #pragma unroll
            for (int df = 0; df < 8; df++) {
                int col = (df << 3) + (l4 << 1);
                float2 vo = make_float2(o[mf][df][rr * 2] * inv,
                                        o[mf][df][rr * 2 + 1] * inv);
                *(float2*)&out[base + col] = vo;
            }
        }
    }
}

// ---------------------------------------------------------------------------
extern "C" void kernel_launch(void* const* d_in, const int* in_sizes, int n_in,
                              void* d_out, int out_size)
{
    const float* x1   = (const float*)d_in[0];
    const float* x2   = (const float*)d_in[1];
    const float* wq   = (const float*)d_in[2];
    const float* bq   = (const float*)d_in[3];
    const float* wkv  = (const float*)d_in[4];
    const float* bkv  = (const float*)d_in[5];
    const float* gmq  = (const float*)d_in[6];
    const float* btq  = (const float*)d_in[7];
    const float* gmk  = (const float*)d_in[8];
    const float* btk  = (const float*)d_in[9];
    float* out = (float*)d_out;

    cudaFuncSetAttribute(attn_kernel, cudaFuncAttributeMaxDynamicSharedMemorySize, ATTN_SMEM);
    cudaFuncSetAttribute(proj_kernel, cudaFuncAttributeMaxDynamicSharedMemorySize, PROJ_SMEM);

    prep_all<<<19456, 256>>>(x1, x2, wq, wkv);

    proj_kernel<<<dim3(24, MM / 128), 128, PROJ_SMEM>>>(bq, bkv, gmq, btq, gmk, btk);

    attn_kernel<<<dim3(NN / 128, BB * HH), 128, ATTN_SMEM>>>(out);
}